// round 2
// baseline (speedup 1.0000x reference)
#include <cuda_runtime.h>
#include <math.h>

#define Bb   512
#define Dd   64
#define Tt   256
#define RNN  100
#define G3   300
#define RPB  4
#define NTHR 320

__device__ float g_states[Tt*Bb*65];
__device__ float g_gib[Tt*Bb*G3];
__device__ float g_gif[Tt*Bb*G3];
__device__ float g_dict[258*Bb*RNN];
__device__ int   g_obs[Tt];

__device__ __forceinline__ float sigm(float x){ return 1.f/(1.f+expf(-x)); }

// one GRU cell for 4 rows: gh = h@U + b1 (300 thr), then gates (400 elems).
// h laid out [4][100] in smem, 16B aligned. gi stride per row = giStride (0 => shared bias vector).
__device__ __forceinline__ void gru_cell4(const float* __restrict__ U, const float* gi, int giStride,
                                          float bias1, float* h, float* gh, int tid){
    if (tid < G3){
        float a0=bias1,a1=bias1,a2=bias1,a3=bias1;
        const float4* h0=(const float4*)(h);
        const float4* h1=(const float4*)(h+RNN);
        const float4* h2=(const float4*)(h+2*RNN);
        const float4* h3=(const float4*)(h+3*RNN);
        #pragma unroll 5
        for (int k4=0;k4<RNN/4;k4++){
            float u0=U[(4*k4+0)*G3+tid];
            float u1=U[(4*k4+1)*G3+tid];
            float u2=U[(4*k4+2)*G3+tid];
            float u3=U[(4*k4+3)*G3+tid];
            float4 v0=h0[k4], v1=h1[k4], v2=h2[k4], v3=h3[k4];
            a0=fmaf(v0.x,u0,a0); a0=fmaf(v0.y,u1,a0); a0=fmaf(v0.z,u2,a0); a0=fmaf(v0.w,u3,a0);
            a1=fmaf(v1.x,u0,a1); a1=fmaf(v1.y,u1,a1); a1=fmaf(v1.z,u2,a1); a1=fmaf(v1.w,u3,a1);
            a2=fmaf(v2.x,u0,a2); a2=fmaf(v2.y,u1,a2); a2=fmaf(v2.z,u2,a2); a2=fmaf(v2.w,u3,a2);
            a3=fmaf(v3.x,u0,a3); a3=fmaf(v3.y,u1,a3); a3=fmaf(v3.z,u2,a3); a3=fmaf(v3.w,u3,a3);
        }
        gh[tid]=a0; gh[G3+tid]=a1; gh[2*G3+tid]=a2; gh[3*G3+tid]=a3;
    }
    __syncthreads();
    for (int i=tid;i<RPB*RNN;i+=NTHR){
        int r=i/RNN, j=i-r*RNN;
        const float* g=gi+r*giStride;
        const float* gr=gh+r*G3;
        float z =sigm(g[j]      + gr[j]);
        float rr=sigm(g[j+RNN]  + gr[j+RNN]);
        float n =tanhf(g[j+2*RNN] + rr*gr[j+2*RNN]);
        h[i]=z*h[i]+(1.f-z)*n;
    }
    __syncthreads();
}

__global__ void k_sched(const float* __restrict__ a){
    int t=threadIdx.x;
    if (t<Tt) g_obs[t] = (a[t*3+2] > 0.5f) ? 1 : 0;   // a[0,0,t,2]
}

__global__ void k_states(const float* __restrict__ a){
    int idx=blockIdx.x*blockDim.x+threadIdx.x;
    if (idx>=Tt*Bb*65) return;
    int c=idx%65; int b=(idx/65)%Bb; int t=idx/(65*Bb);
    float v = (c<64) ? a[((b*Dd+c)*Tt+t)*3] : a[((b*Dd+0)*Tt+t)*3+2];
    g_states[(t*Bb+b)*65+c]=v;
}

// gi precompute. mode0: backward, all t>=1 (65-dim input). mode1: forward, t==0 or observed (cols 1..64).
__global__ void __launch_bounds__(NTHR) k_gi(const float* __restrict__ gruW, const float* __restrict__ gruB,
                                             const float* __restrict__ bgruW, const float* __restrict__ bgruB){
    __shared__ float xs[16*65];
    int t=blockIdx.x>>5;
    int b0=(blockIdx.x&31)*16;
    int mode=blockIdx.y;
    if (mode==0 && t==0) return;
    if (mode==1 && t>0 && !g_obs[t]) return;
    int tid=threadIdx.x;
    for (int i=tid;i<16*65;i+=NTHR){
        int r=i/65,c=i-r*65;
        xs[i]=g_states[(t*Bb+b0+r)*65+c];
    }
    __syncthreads();
    if (tid>=G3) return;
    const float* W = mode? gruW : bgruW;
    float bias     = mode? gruB[tid] : bgruB[tid];
    int Kk         = mode? 64 : 65;
    int xo         = mode? 1 : 0;
    float acc[16];
    #pragma unroll
    for (int r=0;r<16;r++) acc[r]=bias;
    for (int k=0;k<Kk;k++){
        float w=W[k*G3+tid];
        #pragma unroll
        for (int r=0;r<16;r++) acc[r]=fmaf(xs[r*65+k+xo],w,acc[r]);
    }
    float* out = mode? g_gif : g_gib;
    #pragma unroll
    for (int r=0;r<16;r++) out[(t*Bb+b0+r)*G3+tid]=acc[r];
}

__global__ void __launch_bounds__(NTHR) k_back(const float* __restrict__ bgruU, const float* __restrict__ bgruB){
    extern __shared__ float sm[];
    float* sU  =sm;          // 30000
    float* gh_s=sU+30000;    // 1200
    float* gi_s=gh_s+1200;   // 1200
    float* h_s =gi_s+1200;   // 400
    int tid=threadIdx.x;
    int b0=blockIdx.x*RPB;
    for (int i=tid;i<RNN*G3;i+=NTHR) sU[i]=bgruU[i];
    for (int i=tid;i<RPB*RNN;i+=NTHR) h_s[i]=0.f;
    float bb1=(tid<G3)?bgruB[G3+tid]:0.f;
    __syncthreads();
    for (int t=Tt-1;t>=1;t--){
        for (int i=tid;i<RPB*RNN;i+=NTHR)
            g_dict[((t+1)*Bb+b0+i/RNN)*RNN+(i%RNN)]=h_s[i];
        for (int i=tid;i<RPB*G3;i+=NTHR)
            gi_s[i]=g_gib[(t*Bb+b0+i/G3)*G3+(i%G3)];
        __syncthreads();
        gru_cell4(sU, gi_s, G3, bb1, h_s, gh_s, tid);
    }
}

__global__ void __launch_bounds__(NTHR) k_fwd(
        const float* __restrict__ gruW, const float* __restrict__ gruU, const float* __restrict__ gruB,
        const float* __restrict__ bgruW, const float* __restrict__ bgruU, const float* __restrict__ bgruB,
        const float* __restrict__ decW, const float* __restrict__ decB,
        const float* __restrict__ meanW, const float* __restrict__ meanB){
    extern __shared__ float sm[];
    float* sUg  =sm;            // 30000
    float* sWg  =sUg+30000;     // 19200
    float* gh_s =sWg+19200;     // 1200
    float* gi_s =gh_s+1200;     // 1200
    float* h_s  =gi_s+1200;     // 400
    float* hb_s =h_s+400;       // 400
    float* xs   =hb_s+400;      // 260
    float* dec_s=xs+260;        // 200
    float* sb0  =dec_s+200;     // 300
    int tid=threadIdx.x;
    int b0=blockIdx.x*RPB;

    for (int i=tid;i<RNN*G3;i+=NTHR) sUg[i]=gruU[i];
    for (int i=tid;i<64*G3;i+=NTHR)  sWg[i]=gruW[i];
    if (tid<G3) sb0[tid]=bgruB[tid];
    float gb0=(tid<G3)?gruB[tid]:0.f;
    float gb1=(tid<G3)?gruB[G3+tid]:0.f;
    float bb1=(tid<G3)?bgruB[G3+tid]:0.f;
    for (int i=tid;i<RPB*RNN;i+=NTHR) h_s[i]=0.f;

    unsigned char obs[Tt];
    for (int t2=0;t2<Tt;t2++) obs[t2]=(unsigned char)g_obs[t2];
    __syncthreads();

    // h = gru_cell(states[0][:,1:], 0)
    for (int i=tid;i<RPB*G3;i+=NTHR)
        gi_s[i]=g_gif[(0*Bb+b0+i/G3)*G3+(i%G3)];
    __syncthreads();
    gru_cell4(sUg, gi_s, G3, gb1, h_s, gh_s, tid);

    int curr_p=0;
    while (curr_p < Tt-1){
        if (obs[curr_p+1]){
            curr_p++;
            for (int i=tid;i<RPB*G3;i+=NTHR)
                gi_s[i]=g_gif[(curr_p*Bb+b0+i/G3)*G3+(i%G3)];
            __syncthreads();
            gru_cell4(sUg, gi_s, G3, gb1, h_s, gh_s, tid);
        } else {
            int next_p=curr_p+1;
            while (next_p<Tt && !obs[next_p]) next_p++;
            int step=1;
            while (curr_p+2*step<=next_p && step<=8) step<<=1;
            if (step>1) step>>=1;
            int lvl = (step==8)?3:(step==4)?2:(step==2)?1:0;
            int tf = curr_p+step;
            // hb = dict[curr_p+2*step]
            for (int i=tid;i<RPB*RNN;i+=NTHR)
                hb_s[i]=g_dict[((curr_p+2*step)*Bb+b0+i/RNN)*RNN+(i%RNN)];
            __syncthreads();
            // dec = relu([h,hb] @ decW[lvl] + decB[lvl])
            const float* dW=decW+lvl*200*50;
            for (int i=tid;i<RPB*50;i+=NTHR){
                int r=i/50, j=i-r*50;
                float acc=decB[lvl*50+j];
                for (int k=0;k<RNN;k++) acc=fmaf(h_s[r*RNN+k], dW[k*50+j], acc);
                for (int k=0;k<RNN;k++) acc=fmaf(hb_s[r*RNN+k], dW[(RNN+k)*50+j], acc);
                dec_s[i]=fmaxf(acc,0.f);
            }
            __syncthreads();
            // mean -> new_state (xs) + g_states
            const float* mW=meanW+lvl*50*64;
            for (int i=tid;i<RPB*64;i+=NTHR){
                int r=i/64, d=i-r*64;
                float acc=meanB[lvl*64+d];
                for (int k=0;k<50;k++) acc=fmaf(dec_s[r*50+k], mW[k*64+d], acc);
                xs[r*65+d]=acc;
                g_states[(tf*Bb+b0+r)*65+d]=acc;
            }
            if (tid<RPB){ xs[tid*65+64]=1.f; g_states[(tf*Bb+b0+tid)*65+64]=1.f; }
            __syncthreads();
            // forward gi for the new state (cols 1..64)
            if (tid<G3){
                for (int r=0;r<RPB;r++){
                    float acc=gb0;
                    for (int k=0;k<64;k++) acc=fmaf(xs[r*65+1+k], sWg[k*G3+tid], acc);
                    g_gif[(tf*Bb+b0+r)*G3+tid]=acc;
                }
            }
            if (step>1){
                int right=curr_p+step, left=curr_p+step/2;
                if (tid<G3){
                    for (int r=0;r<RPB;r++){
                        float acc=sb0[tid];
                        for (int k=0;k<65;k++) acc=fmaf(xs[r*65+k], bgruW[k*G3+tid], acc);
                        gi_s[r*G3+tid]=acc;
                    }
                }
                for (int i=tid;i<RPB*RNN;i+=NTHR)
                    hb_s[i]=g_dict[((right+1)*Bb+b0+i/RNN)*RNN+(i%RNN)];
                __syncthreads();
                gru_cell4(bgruU, gi_s, G3, bb1, hb_s, gh_s, tid);
                for (int i=tid;i<RPB*RNN;i+=NTHR)
                    g_dict[(right*Bb+b0+i/RNN)*RNN+(i%RNN)]=hb_s[i];
                for (int ii=right-1; ii>=left; ii--){
                    gru_cell4(bgruU, sb0, 0, bb1, hb_s, gh_s, tid);
                    for (int i=tid;i<RPB*RNN;i+=NTHR)
                        g_dict[(ii*Bb+b0+i/RNN)*RNN+(i%RNN)]=hb_s[i];
                }
                __syncthreads();
            } else {
                __syncthreads();
            }
            obs[tf]=1;
        }
    }
}

__global__ void k_out(float* __restrict__ out){
    int idx=blockIdx.x*blockDim.x+threadIdx.x;
    if (idx>=Bb*Dd*Tt) return;
    int t=idx%Tt; int d=(idx/Tt)%Dd; int b=idx/(Tt*Dd);
    out[idx]=g_states[(t*Bb+b)*65 + d + 1];   // out takes states cols 1..64
}

extern "C" void kernel_launch(void* const* d_in, const int* in_sizes, int n_in,
                              void* d_out, int out_size){
    const float* a    =(const float*)d_in[0];
    const float* gruW =(const float*)d_in[1];
    const float* gruU =(const float*)d_in[2];
    const float* gruB =(const float*)d_in[3];
    const float* bgruW=(const float*)d_in[4];
    const float* bgruU=(const float*)d_in[5];
    const float* bgruB=(const float*)d_in[6];
    const float* decW =(const float*)d_in[7];
    const float* decB =(const float*)d_in[8];
    const float* meanW=(const float*)d_in[9];
    const float* meanB=(const float*)d_in[10];
    float* out=(float*)d_out;

    cudaFuncSetAttribute(k_back, cudaFuncAttributeMaxDynamicSharedMemorySize, 33800*4);
    cudaFuncSetAttribute(k_fwd,  cudaFuncAttributeMaxDynamicSharedMemorySize, 53160*4);

    k_sched<<<1,256>>>(a);
    k_states<<<(Tt*Bb*65+255)/256,256>>>(a);
    dim3 g2(Tt*32,2);
    k_gi<<<g2,NTHR>>>(gruW,gruB,bgruW,bgruB);
    k_back<<<Bb/RPB,NTHR,33800*4>>>(bgruU,bgruB);
    k_fwd<<<Bb/RPB,NTHR,53160*4>>>(gruW,gruU,gruB,bgruW,bgruU,bgruB,decW,decB,meanW,meanB);
    k_out<<<(Bb*Dd*Tt+255)/256,256>>>(out);
}

// round 4
// speedup vs baseline: 1.1253x; 1.1253x over previous
#include <cuda_runtime.h>
#include <math.h>

#define Bb   512
#define Dd   64
#define Tt   256
#define RNN  100
#define G3   300
#define RPB  4
#define NTHR 640

__device__ float g_states[Tt*Bb*65];
__device__ float g_gib[Tt*Bb*G3];
__device__ float g_gif[Tt*Bb*G3];
__device__ float g_dict[258*Bb*RNN];
__device__ int   g_obs[Tt];

__device__ __forceinline__ float tanh_ap(float x){ float r; asm("tanh.approx.f32 %0, %1;":"=f"(r):"f"(x)); return r; }
__device__ __forceinline__ float sigm2(float x){ return 0.5f + 0.5f*tanh_ap(0.5f*x); }

// one GRU cell for 4 rows, split-k over 600 threads.
// matvec: thread (j = tid%300, kh = tid<300?0:1) accumulates its k-half of
// gh[r][j] = sum_k h[r][k]*U[k][j] into ghp[kh*1200 + r*300 + j].
// gates: 400 threads combine halves, add bias b1s[j], apply gate math, update h.
// caller must __syncthreads() before calling (h and gi must be visible).
__device__ __forceinline__ void gru_cell4(const float* __restrict__ U, const float* gi, int giStride,
                                          const float* __restrict__ b1s, float* h, float* ghp, int tid){
    if (tid < 600){
        int kh = (tid < 300) ? 0 : 1;
        int j  = (tid < 300) ? tid : tid - 300;
        float a0=0.f,a1=0.f,a2=0.f,a3=0.f;
        const float4* h0=(const float4*)(h);
        const float4* h1=(const float4*)(h+RNN);
        const float4* h2=(const float4*)(h+2*RNN);
        const float4* h3=(const float4*)(h+3*RNN);
        int base = kh ? 13 : 0;
        int cnt  = kh ? 12 : 13;
        #pragma unroll
        for (int kk=0; kk<13; kk++){
            if (kk < cnt){
                int k4 = base + kk;
                float u0=U[(4*k4+0)*G3+j];
                float u1=U[(4*k4+1)*G3+j];
                float u2=U[(4*k4+2)*G3+j];
                float u3=U[(4*k4+3)*G3+j];
                float4 v0=h0[k4], v1=h1[k4], v2=h2[k4], v3=h3[k4];
                a0=fmaf(v0.x,u0,a0); a0=fmaf(v0.y,u1,a0); a0=fmaf(v0.z,u2,a0); a0=fmaf(v0.w,u3,a0);
                a1=fmaf(v1.x,u0,a1); a1=fmaf(v1.y,u1,a1); a1=fmaf(v1.z,u2,a1); a1=fmaf(v1.w,u3,a1);
                a2=fmaf(v2.x,u0,a2); a2=fmaf(v2.y,u1,a2); a2=fmaf(v2.z,u2,a2); a2=fmaf(v2.w,u3,a2);
                a3=fmaf(v3.x,u0,a3); a3=fmaf(v3.y,u1,a3); a3=fmaf(v3.z,u2,a3); a3=fmaf(v3.w,u3,a3);
            }
        }
        ghp[kh*1200      +j]=a0; ghp[kh*1200+300+j]=a1;
        ghp[kh*1200+600+j]=a2; ghp[kh*1200+900+j]=a3;
    }
    __syncthreads();
    for (int i=tid;i<RPB*RNN;i+=NTHR){
        int r=i/RNN, jj=i-r*RNN;
        float b_z=b1s[jj], b_r=b1s[jj+100], b_n=b1s[jj+200];
        float ghz=ghp[r*300+jj]     +ghp[1200+r*300+jj]     +b_z;
        float ghr=ghp[r*300+jj+100] +ghp[1200+r*300+jj+100] +b_r;
        float ghn=ghp[r*300+jj+200] +ghp[1200+r*300+jj+200] +b_n;
        const float* g=gi+r*giStride;
        float z =sigm2(g[jj]      + ghz);
        float rr=sigm2(g[jj+100]  + ghr);
        float n =tanh_ap(g[jj+200] + rr*ghn);
        h[i]=z*h[i]+(1.f-z)*n;
    }
    __syncthreads();
}

__global__ void k_sched(const float* __restrict__ a){
    int t=threadIdx.x;
    if (t<Tt) g_obs[t] = (a[t*3+2] > 0.5f) ? 1 : 0;   // a[0,0,t,2]
}

__global__ void k_states(const float* __restrict__ a){
    int idx=blockIdx.x*blockDim.x+threadIdx.x;
    if (idx>=Tt*Bb*65) return;
    int c=idx%65; int b=(idx/65)%Bb; int t=idx/(65*Bb);
    float v = (c<64) ? a[((b*Dd+c)*Tt+t)*3] : a[((b*Dd+0)*Tt+t)*3+2];
    g_states[(t*Bb+b)*65+c]=v;
}

// gi precompute. mode0: backward, all t>=1 (65-dim input). mode1: forward, t==0 or observed (cols 1..64).
__global__ void __launch_bounds__(320) k_gi(const float* __restrict__ gruW, const float* __restrict__ gruB,
                                            const float* __restrict__ bgruW, const float* __restrict__ bgruB){
    __shared__ float xs[16*65];
    int t=blockIdx.x>>5;
    int b0=(blockIdx.x&31)*16;
    int mode=blockIdx.y;
    if (mode==0 && t==0) return;
    if (mode==1 && t>0 && !g_obs[t]) return;
    int tid=threadIdx.x;
    for (int i=tid;i<16*65;i+=320){
        int r=i/65,c=i-r*65;
        xs[i]=g_states[(t*Bb+b0+r)*65+c];
    }
    __syncthreads();
    if (tid>=G3) return;
    const float* W = mode? gruW : bgruW;
    float bias     = mode? gruB[tid] : bgruB[tid];
    int Kk         = mode? 64 : 65;
    int xo         = mode? 1 : 0;
    float acc[16];
    #pragma unroll
    for (int r=0;r<16;r++) acc[r]=bias;
    for (int k=0;k<Kk;k++){
        float w=W[k*G3+tid];
        #pragma unroll
        for (int r=0;r<16;r++) acc[r]=fmaf(xs[r*65+k+xo],w,acc[r]);
    }
    float* out = mode? g_gif : g_gib;
    #pragma unroll
    for (int r=0;r<16;r++) out[(t*Bb+b0+r)*G3+tid]=acc[r];
}

// smem: sU 30000 | ghp 2400 | gi_s 1200 | h_s 400 | sbb1 300 = 34300
__global__ void __launch_bounds__(NTHR,1) k_back(const float* __restrict__ bgruU, const float* __restrict__ bgruB){
    extern __shared__ float sm[];
    float* sU  =sm;
    float* ghp =sU+30000;
    float* gi_s=ghp+2400;
    float* h_s =gi_s+1200;
    float* sbb1=h_s+400;
    int tid=threadIdx.x;
    int b0=blockIdx.x*RPB;
    for (int i=tid;i<RNN*G3;i+=NTHR) sU[i]=bgruU[i];
    for (int i=tid;i<RPB*RNN;i+=NTHR) h_s[i]=0.f;
    if (tid<G3) sbb1[tid]=bgruB[G3+tid];
    __syncthreads();
    for (int t=Tt-1;t>=1;t--){
        for (int i=tid;i<RPB*RNN;i+=NTHR)
            g_dict[((t+1)*Bb+b0+i/RNN)*RNN+(i%RNN)]=h_s[i];
        for (int i=tid;i<RPB*G3;i+=NTHR)
            gi_s[i]=g_gib[(t*Bb+b0+i/G3)*G3+(i%G3)];
        __syncthreads();
        gru_cell4(sU, gi_s, G3, sbb1, h_s, ghp, tid);
    }
}

// smem: sUg 30000 | sWg 19200 | ghp 2400 | gi_s 1200 | h_s 400 | hb_s 400
//       | xs 260 | dec_s 200 | sb0 300 | sbb1 300 | sgb1 300 = 54960
__global__ void __launch_bounds__(NTHR,1) k_fwd(
        const float* __restrict__ gruW, const float* __restrict__ gruU, const float* __restrict__ gruB,
        const float* __restrict__ bgruW, const float* __restrict__ bgruU, const float* __restrict__ bgruB,
        const float* __restrict__ decW, const float* __restrict__ decB,
        const float* __restrict__ meanW, const float* __restrict__ meanB){
    extern __shared__ float sm[];
    float* sUg  =sm;
    float* sWg  =sUg+30000;
    float* ghp  =sWg+19200;
    float* gi_s =ghp+2400;
    float* h_s  =gi_s+1200;
    float* hb_s =h_s+400;
    float* xs   =hb_s+400;
    float* dec_s=xs+260;
    float* sb0  =dec_s+200;
    float* sbb1 =sb0+300;
    float* sgb1 =sbb1+300;
    int tid=threadIdx.x;
    int b0=blockIdx.x*RPB;

    for (int i=tid;i<RNN*G3;i+=NTHR) sUg[i]=gruU[i];
    for (int i=tid;i<64*G3;i+=NTHR)  sWg[i]=gruW[i];
    if (tid<G3){ sb0[tid]=bgruB[tid]; sbb1[tid]=bgruB[G3+tid]; sgb1[tid]=gruB[G3+tid]; }
    float gb0=(tid<G3)?gruB[tid]:0.f;
    for (int i=tid;i<RPB*RNN;i+=NTHR) h_s[i]=0.f;

    unsigned char obs[Tt];
    for (int t2=0;t2<Tt;t2++) obs[t2]=(unsigned char)g_obs[t2];
    __syncthreads();

    // h = gru_cell(states[0][:,1:], 0)
    for (int i=tid;i<RPB*G3;i+=NTHR)
        gi_s[i]=g_gif[(0*Bb+b0+i/G3)*G3+(i%G3)];
    __syncthreads();
    gru_cell4(sUg, gi_s, G3, sgb1, h_s, ghp, tid);

    int curr_p=0;
    while (curr_p < Tt-1){
        if (obs[curr_p+1]){
            curr_p++;
            for (int i=tid;i<RPB*G3;i+=NTHR)
                gi_s[i]=g_gif[(curr_p*Bb+b0+i/G3)*G3+(i%G3)];
            __syncthreads();
            gru_cell4(sUg, gi_s, G3, sgb1, h_s, ghp, tid);
        } else {
            int next_p=curr_p+1;
            while (next_p<Tt && !obs[next_p]) next_p++;
            int step=1;
            while (curr_p+2*step<=next_p && step<=8) step<<=1;
            if (step>1) step>>=1;
            int lvl = (step==8)?3:(step==4)?2:(step==2)?1:0;
            int tf = curr_p+step;
            // hb = dict[curr_p+2*step]
            for (int i=tid;i<RPB*RNN;i+=NTHR)
                hb_s[i]=g_dict[((curr_p+2*step)*Bb+b0+i/RNN)*RNN+(i%RNN)];
            __syncthreads();
            // dec = relu([h,hb] @ decW[lvl] + decB[lvl])
            const float* dW=decW+lvl*200*50;
            for (int i=tid;i<RPB*50;i+=NTHR){
                int r=i/50, j=i-r*50;
                float acc=decB[lvl*50+j];
                for (int k=0;k<RNN;k++) acc=fmaf(h_s[r*RNN+k], dW[k*50+j], acc);
                for (int k=0;k<RNN;k++) acc=fmaf(hb_s[r*RNN+k], dW[(RNN+k)*50+j], acc);
                dec_s[i]=fmaxf(acc,0.f);
            }
            __syncthreads();
            // mean -> new_state (xs) + g_states
            const float* mW=meanW+lvl*50*64;
            for (int i=tid;i<RPB*64;i+=NTHR){
                int r=i/64, d=i-r*64;
                float acc=meanB[lvl*64+d];
                for (int k=0;k<50;k++) acc=fmaf(dec_s[r*50+k], mW[k*64+d], acc);
                xs[r*65+d]=acc;
                g_states[(tf*Bb+b0+r)*65+d]=acc;
            }
            if (tid<RPB){ xs[tid*65+64]=1.f; g_states[(tf*Bb+b0+tid)*65+64]=1.f; }
            __syncthreads();
            // forward gi for the new state (cols 1..64)
            if (tid<G3){
                for (int r=0;r<RPB;r++){
                    float acc=gb0;
                    for (int k=0;k<64;k++) acc=fmaf(xs[r*65+1+k], sWg[k*G3+tid], acc);
                    g_gif[(tf*Bb+b0+r)*G3+tid]=acc;
                }
            }
            if (step>1){
                int right=curr_p+step, left=curr_p+step/2;
                if (tid<G3){
                    for (int r=0;r<RPB;r++){
                        float acc=sb0[tid];
                        for (int k=0;k<65;k++) acc=fmaf(xs[r*65+k], bgruW[k*G3+tid], acc);
                        gi_s[r*G3+tid]=acc;
                    }
                }
                for (int i=tid;i<RPB*RNN;i+=NTHR)
                    hb_s[i]=g_dict[((right+1)*Bb+b0+i/RNN)*RNN+(i%RNN)];
                __syncthreads();
                gru_cell4(bgruU, gi_s, G3, sbb1, hb_s, ghp, tid);
                for (int i=tid;i<RPB*RNN;i+=NTHR)
                    g_dict[(right*Bb+b0+i/RNN)*RNN+(i%RNN)]=hb_s[i];
                for (int ii=right-1; ii>=left; ii--){
                    gru_cell4(bgruU, sb0, 0, sbb1, hb_s, ghp, tid);
                    for (int i=tid;i<RPB*RNN;i+=NTHR)
                        g_dict[(ii*Bb+b0+i/RNN)*RNN+(i%RNN)]=hb_s[i];
                }
                __syncthreads();
            } else {
                __syncthreads();
            }
            obs[tf]=1;
        }
    }
}

__global__ void k_out(float* __restrict__ out){
    int idx=blockIdx.x*blockDim.x+threadIdx.x;
    if (idx>=Bb*Dd*Tt) return;
    int t=idx%Tt; int d=(idx/Tt)%Dd; int b=idx/(Tt*Dd);
    out[idx]=g_states[(t*Bb+b)*65 + d + 1];
}

extern "C" void kernel_launch(void* const* d_in, const int* in_sizes, int n_in,
                              void* d_out, int out_size){
    const float* a    =(const float*)d_in[0];
    const float* gruW =(const float*)d_in[1];
    const float* gruU =(const float*)d_in[2];
    const float* gruB =(const float*)d_in[3];
    const float* bgruW=(const float*)d_in[4];
    const float* bgruU=(const float*)d_in[5];
    const float* bgruB=(const float*)d_in[6];
    const float* decW =(const float*)d_in[7];
    const float* decB =(const float*)d_in[8];
    const float* meanW=(const float*)d_in[9];
    const float* meanB=(const float*)d_in[10];
    float* out=(float*)d_out;

    cudaFuncSetAttribute(k_back, cudaFuncAttributeMaxDynamicSharedMemorySize, 34300*4);
    cudaFuncSetAttribute(k_fwd,  cudaFuncAttributeMaxDynamicSharedMemorySize, 54960*4);

    k_sched<<<1,256>>>(a);
    k_states<<<(Tt*Bb*65+255)/256,256>>>(a);
    dim3 g2(Tt*32,2);
    k_gi<<<g2,320>>>(gruW,gruB,bgruW,bgruB);
    k_back<<<Bb/RPB,NTHR,34300*4>>>(bgruU,bgruB);
    k_fwd<<<Bb/RPB,NTHR,54960*4>>>(gruW,gruU,gruB,bgruW,bgruU,bgruB,decW,decB,meanW,meanB);
    k_out<<<(Bb*Dd*Tt+255)/256,256>>>(out);
}

// round 7
// speedup vs baseline: 1.2398x; 1.1018x over previous
#include <cuda_runtime.h>
#include <math.h>

#define Bb   512
#define Dd   64
#define Tt   256
#define RNN  100
#define G3   300
#define RPB  4
#define NTHR 928

typedef unsigned long long u64;

__device__ float g_states[Tt*Bb*65];
__device__ float g_gib[Tt*Bb*G3];
__device__ float g_gif[Tt*Bb*G3];
__device__ float g_dict[257*128*400];   // interleaved [key][blk][k*4+r]
__device__ int   g_obs[Tt];

__device__ __forceinline__ float tanh_ap(float x){ float r; asm("tanh.approx.f32 %0, %1;":"=f"(r):"f"(x)); return r; }
__device__ __forceinline__ float sigm2(float x){ return 0.5f + 0.5f*tanh_ap(0.5f*x); }
__device__ __forceinline__ u64 ffma2(u64 a,u64 b,u64 c){ u64 d; asm("fma.rn.f32x2 %0, %1, %2, %3;":"=l"(d):"l"(a),"l"(b),"l"(c)); return d; }
__device__ __forceinline__ u64 dup2(float x){ u64 d; asm("mov.b64 %0, {%1, %1};":"=l"(d):"f"(x)); return d; }

__device__ __forceinline__ void st_ghp(float* ghp,int kh,int j,u64 a01,u64 a23){
    float f0,f1,f2,f3;
    asm("mov.b64 {%0,%1},%2;":"=f"(f0),"=f"(f1):"l"(a01));
    asm("mov.b64 {%0,%1},%2;":"=f"(f2),"=f"(f3):"l"(a23));
    float* p=ghp+kh*1200+j;
    p[0]=f0; p[300]=f1; p[600]=f2; p[900]=f3;
}

// packed matvec over interleaved h4f[k*4+r]; partials into ghp[kh][r][j]
__device__ __forceinline__ void mv_reg(const float (&u)[34], const float* h4f, float* ghp,
                                       int tid,int j,int kh,int k0,int kc){
    if (tid<900){
        u64 a01=0ull, a23=0ull;
        const ulonglong2* h2=(const ulonglong2*)h4f;
        #pragma unroll
        for (int i=0;i<34;i++) if (i<kc){
            u64 w=dup2(u[i]);
            ulonglong2 x=h2[k0+i];
            a01=ffma2(x.x,w,a01); a23=ffma2(x.y,w,a23);
        }
        st_ghp(ghp,kh,j,a01,a23);
    }
}
__device__ __forceinline__ void mv_smem(const float* __restrict__ U, const float* h4f, float* ghp,
                                        int tid,int j,int kh,int k0,int kc){
    if (tid<900){
        u64 a01=0ull, a23=0ull;
        const ulonglong2* h2=(const ulonglong2*)h4f;
        #pragma unroll
        for (int i=0;i<34;i++) if (i<kc){
            u64 w=dup2(U[(k0+i)*G3+j]);
            ulonglong2 x=h2[k0+i];
            a01=ffma2(x.x,w,a01); a23=ffma2(x.y,w,a23);
        }
        st_ghp(ghp,kh,j,a01,a23);
    }
}

// gates: combine 3 k-planes + bias, update h4f[jj*4+r], optional dict store.
__device__ __forceinline__ void gates4(const float* ghp, const float* gi, int giStride,
                                       const float* b1s, float* h4f, float* dictDst, int tid){
    if (tid<400){
        int jj=tid>>2, r=tid&3;
        int o=r*300+jj;
        float ghz=ghp[o]    +ghp[1200+o]    +ghp[2400+o]    +b1s[jj];
        float ghr=ghp[o+100]+ghp[1200+o+100]+ghp[2400+o+100]+b1s[jj+100];
        float ghn=ghp[o+200]+ghp[1200+o+200]+ghp[2400+o+200]+b1s[jj+200];
        const float* g=gi+r*giStride;
        float z =sigm2(g[jj]     + ghz);
        float rr=sigm2(g[jj+100] + ghr);
        float n =tanh_ap(g[jj+200] + rr*ghn);
        float hn=z*h4f[tid]+(1.f-z)*n;
        h4f[tid]=hn;
        if (dictDst) dictDst[tid]=hn;
    }
}

__global__ void k_sched(const float* __restrict__ a){
    int t=threadIdx.x;
    if (t<Tt) g_obs[t] = (a[t*3+2] > 0.5f) ? 1 : 0;
}

__global__ void k_states(const float* __restrict__ a){
    int idx=blockIdx.x*blockDim.x+threadIdx.x;
    if (idx>=Tt*Bb*65) return;
    int c=idx%65; int b=(idx/65)%Bb; int t=idx/(65*Bb);
    float v=(c<64)? a[((b*Dd+c)*Tt+t)*3] : a[((b*Dd)*Tt+t)*3+2];
    g_states[(t*Bb+b)*65+c]=v;
}

__global__ void __launch_bounds__(320) k_gi(const float* __restrict__ gruW, const float* __restrict__ gruB,
                                            const float* __restrict__ bgruW, const float* __restrict__ bgruB){
    __shared__ float xs[16*65];
    int t=blockIdx.x>>5;
    int b0=(blockIdx.x&31)*16;
    int mode=blockIdx.y;
    if (mode==0 && t==0) return;
    if (mode==1 && t>0 && !g_obs[t]) return;
    int tid=threadIdx.x;
    for (int i=tid;i<16*65;i+=320){
        int r=i/65,c=i-r*65;
        xs[i]=g_states[(t*Bb+b0+r)*65+c];
    }
    __syncthreads();
    if (tid>=G3) return;
    const float* W = mode? gruW : bgruW;
    float bias     = mode? gruB[tid] : bgruB[tid];
    int Kk         = mode? 64 : 65;
    int xo         = mode? 1 : 0;
    float acc[16];
    #pragma unroll
    for (int r=0;r<16;r++) acc[r]=bias;
    for (int k=0;k<Kk;k++){
        float w=W[k*G3+tid];
        #pragma unroll
        for (int r=0;r<16;r++) acc[r]=fmaf(xs[r*65+k+xo],w,acc[r]);
    }
    float* out = mode? g_gif : g_gib;
    #pragma unroll
    for (int r=0;r<16;r++) out[(t*Bb+b0+r)*G3+tid]=acc[r];
}

__global__ void __launch_bounds__(NTHR,1) k_back(const float* __restrict__ bgruU, const float* __restrict__ bgruB){
    __shared__ float ghp[3600];
    __shared__ float gi_s[1200];
    __shared__ __align__(16) float h4f[400];
    __shared__ float sbb1[300];
    int tid=threadIdx.x, blk=blockIdx.x, b0=blk*RPB;
    int kh=tid/300, j=tid-kh*300;
    int k0c=(kh==0)?0:((kh==1)?34:67);
    int kcC=(kh==0)?34:33;
    float uB[34];
    if (tid<900){
        #pragma unroll
        for (int i=0;i<34;i++) if (i<kcC) uB[i]=bgruU[(k0c+i)*G3+j];
    }
    if (tid<G3) sbb1[tid]=bgruB[G3+tid];
    if (tid<400){ h4f[tid]=0.f; g_dict[(256*128+blk)*400+tid]=0.f; }
    __syncthreads();
    for (int t=Tt-1;t>=1;t--){
        for (int i=tid;i<1200;i+=NTHR) gi_s[i]=g_gib[(t*Bb+b0)*G3+i];
        mv_reg(uB,h4f,ghp,tid,j,kh,k0c,kcC);
        __syncthreads();
        gates4(ghp,gi_s,G3,sbb1,h4f,(t>=2)? g_dict+(t*128+blk)*400 : (float*)0, tid);
        __syncthreads();
    }
}

// dyn smem layout (words): sUg 0 | sWg 30000 | ghp 49200 | gi_s 52800 | h4f 54000
// | hb4f 54400 | xs 54800 | dec_s 55060 | decp 55260 | sb0 56060 | sbb1 56360
// | sgb1 56660 | sgb0 56960 | total 57260
__global__ void __launch_bounds__(NTHR,1) k_fwd(
        const float* __restrict__ gruW, const float* __restrict__ gruU, const float* __restrict__ gruB,
        const float* __restrict__ bgruW, const float* __restrict__ bgruU, const float* __restrict__ bgruB,
        const float* __restrict__ decW, const float* __restrict__ decB,
        const float* __restrict__ meanW, const float* __restrict__ meanB){
    extern __shared__ float sm[];
    float* sUg =sm;
    float* sWg =sm+30000;
    float* ghp =sm+49200;
    float* gi_s=sm+52800;
    float* h4f =sm+54000;
    float* hb4f=sm+54400;
    float* xs  =sm+54800;
    float* dec_s=sm+55060;
    float* decp=sm+55260;
    float* sb0 =sm+56060;
    float* sbb1=sm+56360;
    float* sgb1=sm+56660;
    float* sgb0=sm+56960;
    __shared__ int obs_s[Tt];

    int tid=threadIdx.x, blk=blockIdx.x, b0=blk*RPB;
    int kh=tid/300, j=tid-kh*300;
    int k0c=(kh==0)?0:((kh==1)?34:67);
    int kcC=(kh==0)?34:33;
    float uB[34];
    if (tid<900){
        #pragma unroll
        for (int i=0;i<34;i++) if (i<kcC) uB[i]=bgruU[(k0c+i)*G3+j];
    }
    for (int i=tid;i<RNN*G3;i+=NTHR) sUg[i]=gruU[i];
    for (int i=tid;i<64*G3;i+=NTHR)  sWg[i]=gruW[i];
    if (tid<G3){ sb0[tid]=bgruB[tid]; sbb1[tid]=bgruB[G3+tid]; sgb1[tid]=gruB[G3+tid]; sgb0[tid]=gruB[tid]; }
    if (tid<400) h4f[tid]=0.f;
    if (tid<Tt) obs_s[tid]=g_obs[tid];
    __syncthreads();

    // initial cell: t=0
    {
        const float* src=g_gif+(0*Bb+b0)*G3;
        for (int i2=tid;i2<1200;i2+=NTHR) gi_s[i2]=src[i2];
        mv_smem(sUg,h4f,ghp,tid,j,kh,k0c,kcC);
        __syncthreads();
        gates4(ghp,gi_s,G3,sgb1,h4f,(float*)0,tid);
        __syncthreads();
    }

    int curr_p=0;
    while (curr_p < Tt-1){
        if (obs_s[curr_p+1]){
            curr_p++;
            const float* src=g_gif+(curr_p*Bb+b0)*G3;
            for (int i2=tid;i2<1200;i2+=NTHR) gi_s[i2]=src[i2];
            mv_smem(sUg,h4f,ghp,tid,j,kh,k0c,kcC);
            __syncthreads();
            gates4(ghp,gi_s,G3,sgb1,h4f,(float*)0,tid);
            __syncthreads();
        } else {
            int next_p=curr_p+1;
            while (next_p<Tt && !obs_s[next_p]) next_p++;
            int step=1;
            while (curr_p+2*step<=next_p && step<=8) step<<=1;
            if (step>1) step>>=1;
            int lvl=(step==8)?3:((step==4)?2:((step==2)?1:0));
            int tf=curr_p+step;

            if (tid<400) hb4f[tid]=g_dict[((curr_p+2*step)*128+blk)*400+tid];
            __syncthreads();

            // decoder partials: seg owns 50 of the 200 cat[h,hb] inputs
            if (tid<800){
                int seg=tid/200, o=tid-seg*200;
                int r=o/50, jo=o-r*50;
                const float* dW=decW+lvl*10000+(seg*50)*50+jo;
                const float* hsrc=(seg<2)? (h4f+(seg&1)*200) : (hb4f+(seg&1)*200);
                float acc=0.f;
                #pragma unroll 10
                for (int kk=0;kk<50;kk++)
                    acc=fmaf(hsrc[kk*4+r], dW[kk*50], acc);
                decp[seg*200+o]=acc;
            }
            __syncthreads();
            if (tid<200){
                int jo=tid%50;
                float v=decp[tid]+decp[200+tid]+decp[400+tid]+decp[600+tid]+decB[lvl*50+jo];
                dec_s[tid]=fmaxf(v,0.f);
            }
            __syncthreads();
            if (tid<256){
                int dcol=tid&63, r=tid>>6;
                const float* mW=meanW+lvl*3200;
                float acc=meanB[lvl*64+dcol];
                #pragma unroll 10
                for (int k=0;k<50;k++) acc=fmaf(dec_s[r*50+k], mW[k*64+dcol], acc);
                xs[r*65+dcol]=acc;
                g_states[(tf*Bb+b0+r)*65+dcol]=acc;
            }
            if (tid<RPB){ xs[tid*65+64]=1.f; g_states[(tf*Bb+b0+tid)*65+64]=1.f; }
            __syncthreads();

            // forward gi for new state (cols 1..64), split-k over 900 threads
            if (tid<900){
                int k0f=(kh==0)?0:((kh==1)?21:42);
                int kcF=(kh==2)?22:21;
                float a0=0.f,a1=0.f,a2=0.f,a3=0.f;
                for (int i2=0;i2<kcF;i2++){
                    float w=sWg[(k0f+i2)*G3+j];
                    a0=fmaf(xs[1+k0f+i2],w,a0);
                    a1=fmaf(xs[66+k0f+i2],w,a1);
                    a2=fmaf(xs[131+k0f+i2],w,a2);
                    a3=fmaf(xs[196+k0f+i2],w,a3);
                }
                float* p=ghp+kh*1200+j;
                p[0]=a0; p[300]=a1; p[600]=a2; p[900]=a3;
            }
            __syncthreads();
            {
                float* dst=g_gif+(tf*Bb+b0)*G3;
                for (int i2=tid;i2<1200;i2+=NTHR)
                    dst[i2]=ghp[i2]+ghp[1200+i2]+ghp[2400+i2]+sgb0[i2%300];
            }
            if (step>1){
                int right=tf, left=curr_p+step/2;
                __syncthreads();
                // backward gi for new state (all 65 cols)
                if (tid<900){
                    int k0b=(kh==0)?0:((kh==1)?22:44);
                    int kcB=(kh==2)?21:22;
                    float a0=0.f,a1=0.f,a2=0.f,a3=0.f;
                    for (int i2=0;i2<kcB;i2++){
                        float w=bgruW[(k0b+i2)*G3+j];
                        a0=fmaf(xs[k0b+i2],w,a0);
                        a1=fmaf(xs[65+k0b+i2],w,a1);
                        a2=fmaf(xs[130+k0b+i2],w,a2);
                        a3=fmaf(xs[195+k0b+i2],w,a3);
                    }
                    float* p=ghp+kh*1200+j;
                    p[0]=a0; p[300]=a1; p[600]=a2; p[900]=a3;
                }
                if (tid<400) hb4f[tid]=g_dict[((right+1)*128+blk)*400+tid];
                __syncthreads();
                for (int i2=tid;i2<1200;i2+=NTHR)
                    gi_s[i2]=ghp[i2]+ghp[1200+i2]+ghp[2400+i2]+sb0[i2%300];
                __syncthreads();
                // right cell
                mv_reg(uB,hb4f,ghp,tid,j,kh,k0c,kcC);
                __syncthreads();
                gates4(ghp,gi_s,G3,sbb1,hb4f,g_dict+(right*128+blk)*400,tid);
                __syncthreads();
                // zeros-input chain
                for (int ii=right-1; ii>=left; ii--){
                    mv_reg(uB,hb4f,ghp,tid,j,kh,k0c,kcC);
                    __syncthreads();
                    gates4(ghp,sb0,0,sbb1,hb4f,g_dict+(ii*128+blk)*400,tid);
                    __syncthreads();
                }
            }
            __syncthreads();
            obs_s[tf]=1;
        }
    }
}

__global__ void k_out(float* __restrict__ out){
    int idx=blockIdx.x*blockDim.x+threadIdx.x;
    if (idx>=Bb*Dd*Tt) return;
    int t=idx%Tt; int d=(idx/Tt)%Dd; int b=idx/(Tt*Dd);
    out[idx]=g_states[(t*Bb+b)*65 + d + 1];
}

extern "C" void kernel_launch(void* const* d_in, const int* in_sizes, int n_in,
                              void* d_out, int out_size){
    const float* a    =(const float*)d_in[0];
    const float* gruW =(const float*)d_in[1];
    const float* gruU =(const float*)d_in[2];
    const float* gruB =(const float*)d_in[3];
    const float* bgruW=(const float*)d_in[4];
    const float* bgruU=(const float*)d_in[5];
    const float* bgruB=(const float*)d_in[6];
    const float* decW =(const float*)d_in[7];
    const float* decB =(const float*)d_in[8];
    const float* meanW=(const float*)d_in[9];
    const float* meanB=(const float*)d_in[10];
    float* out=(float*)d_out;

    cudaFuncSetAttribute(k_fwd, cudaFuncAttributeMaxDynamicSharedMemorySize, 57260*4);

    k_sched<<<1,256>>>(a);
    k_states<<<(Tt*Bb*65+255)/256,256>>>(a);
    dim3 g2(Tt*32,2);
    k_gi<<<g2,320>>>(gruW,gruB,bgruW,bgruB);
    k_back<<<Bb/RPB,NTHR>>>(bgruU,bgruB);
    k_fwd<<<Bb/RPB,NTHR,57260*4>>>(gruW,gruU,gruB,bgruW,bgruU,bgruB,decW,decB,meanW,meanB);
    k_out<<<(Bb*Dd*Tt+255)/256,256>>>(out);
}

// round 9
// speedup vs baseline: 1.3709x; 1.1057x over previous
#include <cuda_runtime.h>
#include <math.h>

#define Bb   512
#define Dd   64
#define Tt   256
#define RNN  100
#define G3   300
#define RPB  4
#define NTHR 928

typedef unsigned long long u64;

__device__ float g_states[Tt*Bb*65];
__device__ float g_gib[Tt*Bb*G3];
__device__ float g_gif[Tt*Bb*G3];
__device__ float g_dict[257*128*400];   // interleaved [key][blk][k*4+r]
__device__ int   g_obs[Tt];
__device__ float g_Ff[4*50*G3];         // fused fwd-gi  [lvl][k][j]
__device__ float g_Fb[4*50*G3];         // fused bwd-gi  [lvl][k][j]
__device__ float g_bff[4*G3];
__device__ float g_bfb[4*G3];

__device__ __forceinline__ float tanh_ap(float x){ float r; asm("tanh.approx.f32 %0, %1;":"=f"(r):"f"(x)); return r; }
__device__ __forceinline__ float sigm2(float x){ return 0.5f + 0.5f*tanh_ap(0.5f*x); }
__device__ __forceinline__ u64 ffma2(u64 a,u64 b,u64 c){ u64 d; asm("fma.rn.f32x2 %0, %1, %2, %3;":"=l"(d):"l"(a),"l"(b),"l"(c)); return d; }
__device__ __forceinline__ u64 dup2(float x){ u64 d; asm("mov.b64 %0, {%1, %1};":"=l"(d):"f"(x)); return d; }

__device__ __forceinline__ void st_ghp(float* ghp,int kh,int j,u64 a01,u64 a23){
    float f0,f1,f2,f3;
    asm("mov.b64 {%0,%1},%2;":"=f"(f0),"=f"(f1):"l"(a01));
    asm("mov.b64 {%0,%1},%2;":"=f"(f2),"=f"(f3):"l"(a23));
    float* p=ghp+kh*1200+j;
    p[0]=f0; p[300]=f1; p[600]=f2; p[900]=f3;
}

__device__ __forceinline__ void mv_reg(const float (&u)[34], const float* h4f, float* ghp,
                                       int tid,int j,int kh,int k0,int kc){
    if (tid<900){
        u64 a01=0ull, a23=0ull;
        const ulonglong2* h2=(const ulonglong2*)h4f;
        #pragma unroll
        for (int i=0;i<34;i++) if (i<kc){
            u64 w=dup2(u[i]);
            ulonglong2 x=h2[k0+i];
            a01=ffma2(x.x,w,a01); a23=ffma2(x.y,w,a23);
        }
        st_ghp(ghp,kh,j,a01,a23);
    }
}
__device__ __forceinline__ void mv_smem(const float* __restrict__ U, const float* h4f, float* ghp,
                                        int tid,int j,int kh,int k0,int kc){
    if (tid<900){
        u64 a01=0ull, a23=0ull;
        const ulonglong2* h2=(const ulonglong2*)h4f;
        #pragma unroll
        for (int i=0;i<34;i++) if (i<kc){
            u64 w=dup2(U[(k0+i)*G3+j]);
            ulonglong2 x=h2[k0+i];
            a01=ffma2(x.x,w,a01); a23=ffma2(x.y,w,a23);
        }
        st_ghp(ghp,kh,j,a01,a23);
    }
}

__device__ __forceinline__ void gates4(const float* ghp, const float* gi, int giStride,
                                       const float* b1s, float* h4f, float* dictDst, int tid){
    if (tid<400){
        int jj=tid>>2, r=tid&3;
        int o=r*300+jj;
        float ghz=ghp[o]    +ghp[1200+o]    +ghp[2400+o]    +b1s[jj];
        float ghr=ghp[o+100]+ghp[1200+o+100]+ghp[2400+o+100]+b1s[jj+100];
        float ghn=ghp[o+200]+ghp[1200+o+200]+ghp[2400+o+200]+b1s[jj+200];
        const float* g=gi+r*giStride;
        float z =sigm2(g[jj]     + ghz);
        float rr=sigm2(g[jj+100] + ghr);
        float n =tanh_ap(g[jj+200] + rr*ghn);
        float hn=z*h4f[tid]+(1.f-z)*n;
        h4f[tid]=hn;
        if (dictDst) dictDst[tid]=hn;
    }
}

__global__ void k_sched(const float* __restrict__ a){
    int t=threadIdx.x;
    if (t<Tt) g_obs[t] = (a[t*3+2] > 0.5f) ? 1 : 0;
}

__global__ void k_states(const float* __restrict__ a){
    int idx=blockIdx.x*blockDim.x+threadIdx.x;
    if (idx>=Tt*Bb*65) return;
    int c=idx%65; int b=(idx/65)%Bb; int t=idx/(65*Bb);
    float v=(c<64)? a[((b*Dd+c)*Tt+t)*3] : a[((b*Dd)*Tt+t)*3+2];
    g_states[(t*Bb+b)*65+c]=v;
}

// fused fill matrices: Ff[lvl][k][j] = sum_{m=1..63} meanW[k][m]*gruW[m-1][j]
//                      Fb[lvl][k][j] = sum_{m=0..63} meanW[k][m]*bgruW[m][j]
// biases absorb meanB and the ones column.
__global__ void k_fuse(const float* __restrict__ gruW, const float* __restrict__ gruB,
                       const float* __restrict__ bgruW, const float* __restrict__ bgruB,
                       const float* __restrict__ meanW, const float* __restrict__ meanB){
    int lvl=blockIdx.x, j=threadIdx.x;
    if (j>=G3) return;
    int kk=blockIdx.y;
    const float* mW=meanW+lvl*3200;
    const float* mb=meanB+lvl*64;
    if (kk<50){
        float sf=0.f, sb=0.f;
        for (int m=0;m<64;m++){
            float w=mW[kk*64+m];
            if (m>=1) sf=fmaf(w, gruW[(m-1)*G3+j], sf);
            sb=fmaf(w, bgruW[m*G3+j], sb);
        }
        g_Ff[(lvl*50+kk)*G3+j]=sf;
        g_Fb[(lvl*50+kk)*G3+j]=sb;
    } else {
        float bf=gruB[j]+gruW[63*G3+j];
        float bb=bgruB[j]+bgruW[64*G3+j];
        for (int m=0;m<64;m++){
            if (m>=1) bf=fmaf(mb[m], gruW[(m-1)*G3+j], bf);
            bb=fmaf(mb[m], bgruW[m*G3+j], bb);
        }
        g_bff[lvl*G3+j]=bf;
        g_bfb[lvl*G3+j]=bb;
    }
}

__global__ void __launch_bounds__(320) k_gi(const float* __restrict__ gruW, const float* __restrict__ gruB,
                                            const float* __restrict__ bgruW, const float* __restrict__ bgruB){
    __shared__ float xs[16*65];
    int t=blockIdx.x>>5;
    int b0=(blockIdx.x&31)*16;
    int mode=blockIdx.y;
    if (mode==0 && t==0) return;
    if (mode==1 && t>0 && !g_obs[t]) return;
    int tid=threadIdx.x;
    for (int i=tid;i<16*65;i+=320){
        int r=i/65,c=i-r*65;
        xs[i]=g_states[(t*Bb+b0+r)*65+c];
    }
    __syncthreads();
    if (tid>=G3) return;
    const float* W = mode? gruW : bgruW;
    float bias     = mode? gruB[tid] : bgruB[tid];
    int Kk         = mode? 64 : 65;
    int xo         = mode? 1 : 0;
    float acc[16];
    #pragma unroll
    for (int r=0;r<16;r++) acc[r]=bias;
    for (int k=0;k<Kk;k++){
        float w=W[k*G3+tid];
        #pragma unroll
        for (int r=0;r<16;r++) acc[r]=fmaf(xs[r*65+k+xo],w,acc[r]);
    }
    float* out = mode? g_gif : g_gib;
    #pragma unroll
    for (int r=0;r<16;r++) out[(t*Bb+b0+r)*G3+tid]=acc[r];
}

__global__ void __launch_bounds__(NTHR,1) k_back(const float* __restrict__ bgruU, const float* __restrict__ bgruB){
    __shared__ float ghp[3600];
    __shared__ float gi_s[1200];
    __shared__ __align__(16) float h4f[400];
    __shared__ float sbb1[300];
    int tid=threadIdx.x, blk=blockIdx.x, b0=blk*RPB;
    int kh=tid/300, j=tid-kh*300;
    int k0c=(kh==0)?0:((kh==1)?34:67);
    int kcC=(kh==0)?34:33;
    float uB[34];
    if (tid<900){
        #pragma unroll
        for (int i=0;i<34;i++) if (i<kcC) uB[i]=bgruU[(k0c+i)*G3+j];
    }
    if (tid<G3) sbb1[tid]=bgruB[G3+tid];
    if (tid<400){ h4f[tid]=0.f; g_dict[(256*128+blk)*400+tid]=0.f; }
    __syncthreads();
    for (int t=Tt-1;t>=1;t--){
        // prefetch gi into regs; STS after mv so LDG overlaps compute
        const float* src=g_gib+(t*Bb+b0)*G3;
        float f0=src[tid];
        float f1=(tid<272)? src[tid+NTHR] : 0.f;
        mv_reg(uB,h4f,ghp,tid,j,kh,k0c,kcC);
        gi_s[tid]=f0;
        if (tid<272) gi_s[tid+NTHR]=f1;
        __syncthreads();
        gates4(ghp,gi_s,G3,sbb1,h4f,(t>=2)? g_dict+(t*128+blk)*400 : (float*)0, tid);
        __syncthreads();
    }
}

// dyn smem (words): sUg 0..30000 | ghp 30000..33600 | gi_s 33600..34800 | h4f 34800..35200
// | hb4f 35200..35600 | dec4 35600..35800 | decp 35800..36600 | sb0 36600..36900
// | sbb1 36900..37200 | sgb1 37200..37500   total 37500 words = 150000 B
__global__ void __launch_bounds__(NTHR,1) k_fwd(
        const float* __restrict__ gruU, const float* __restrict__ gruB,
        const float* __restrict__ bgruU, const float* __restrict__ bgruB,
        const float* __restrict__ decW, const float* __restrict__ decB,
        const float* __restrict__ meanW, const float* __restrict__ meanB){
    extern __shared__ float sm[];
    float* sUg =sm;
    float* ghp =sm+30000;
    float* gi_s=sm+33600;
    float* h4f =sm+34800;
    float* hb4f=sm+35200;
    float* dec4=sm+35600;
    float* decp=sm+35800;
    float* sb0 =sm+36600;
    float* sbb1=sm+36900;
    float* sgb1=sm+37200;
    __shared__ int obs_s[Tt];

    int tid=threadIdx.x, blk=blockIdx.x, b0=blk*RPB;
    int kh=tid/300, j=tid-kh*300;
    int k0c=(kh==0)?0:((kh==1)?34:67);
    int kcC=(kh==0)?34:33;
    float uB[34];
    if (tid<900){
        #pragma unroll
        for (int i=0;i<34;i++) if (i<kcC) uB[i]=bgruU[(k0c+i)*G3+j];
    }
    for (int i=tid;i<RNN*G3;i+=NTHR) sUg[i]=gruU[i];
    if (tid<G3){ sb0[tid]=bgruB[tid]; sbb1[tid]=bgruB[G3+tid]; sgb1[tid]=gruB[G3+tid]; }
    if (tid<400) h4f[tid]=0.f;
    if (tid<Tt) obs_s[tid]=g_obs[tid];
    __syncthreads();

    bool skip=false;
    // initial forward cell: t=0
    {
        const float* src=g_gif+(0*Bb+b0)*G3;
        float f0=src[tid];
        float f1=(tid<272)? src[tid+NTHR] : 0.f;
        mv_smem(sUg,h4f,ghp,tid,j,kh,k0c,kcC);
        gi_s[tid]=f0;
        if (tid<272) gi_s[tid+NTHR]=f1;
        __syncthreads();
        gates4(ghp,gi_s,G3,sgb1,h4f,(float*)0,tid);
        __syncthreads();
    }

    int curr_p=0;
    while (curr_p < Tt-1){
        if (obs_s[curr_p+1]){
            curr_p++;
            float f0=0.f,f1=0.f;
            if (!skip){
                const float* src=g_gif+(curr_p*Bb+b0)*G3;
                f0=src[tid];
                if (tid<272) f1=src[tid+NTHR];
            }
            mv_smem(sUg,h4f,ghp,tid,j,kh,k0c,kcC);
            if (!skip){
                gi_s[tid]=f0;
                if (tid<272) gi_s[tid+NTHR]=f1;
            }
            skip=false;
            __syncthreads();
            gates4(ghp,gi_s,G3,sgb1,h4f,(float*)0,tid);
            __syncthreads();
        } else {
            int next_p=curr_p+1;
            while (next_p<Tt && !obs_s[next_p]) next_p++;
            int step=1;
            while (curr_p+2*step<=next_p && step<=8) step<<=1;
            if (step>1) step>>=1;
            int lvl=(step==8)?3:((step==4)?2:((step==2)?1:0));
            int tf=curr_p+step;
            int fl=(step>1);

            // P1: hb = dict[curr+2*step]
            if (tid<400) hb4f[tid]=g_dict[((curr_p+2*step)*128+blk)*400+tid];
            __syncthreads();

            // P2: decoder partials over cat[h,hb]
            if (tid<800){
                int seg=tid/200, o=tid-seg*200;
                int r=o/50, jo=o-r*50;
                const float* dW=decW+lvl*10000+(seg*50)*50+jo;
                const float* hsrc=(seg<2)? (h4f+(seg&1)*200) : (hb4f+(seg&1)*200);
                float acc=0.f;
                #pragma unroll 10
                for (int kk=0;kk<50;kk++)
                    acc=fmaf(hsrc[kk*4+r], dW[kk*50], acc);
                decp[seg*200+o]=acc;
            }
            __syncthreads();

            // P3: reduce + relu -> dec4 interleaved [k*4+r]
            if (tid<200){
                int r=tid/50, jo=tid-r*50;
                int o=r*50+jo;
                float v=decp[o]+decp[200+o]+decp[400+o]+decp[600+o]+decB[lvl*50+jo];
                dec4[jo*4+r]=fmaxf(v,0.f);
            }
            __syncthreads();

            // P4: merged — fwd-gi || bwd-gi(if fl) || mean || hb(right+1) prefetch
            if (tid<300){
                u64 a01=dup2(g_bff[lvl*G3+tid]), a23=a01;
                const ulonglong2* dp=(const ulonglong2*)dec4;
                const float* Fp=g_Ff + (lvl*50)*G3 + tid;
                #pragma unroll 10
                for (int k=0;k<50;k++){
                    u64 w=dup2(Fp[k*G3]);
                    ulonglong2 x=dp[k];
                    a01=ffma2(x.x,w,a01); a23=ffma2(x.y,w,a23);
                }
                float f0,f1,f2,f3;
                asm("mov.b64 {%0,%1},%2;":"=f"(f0),"=f"(f1):"l"(a01));
                asm("mov.b64 {%0,%1},%2;":"=f"(f2),"=f"(f3):"l"(a23));
                float* dst=g_gif+(tf*Bb+b0)*G3+tid;
                dst[0]=f0; dst[300]=f1; dst[600]=f2; dst[900]=f3;
                if (!fl){
                    gi_s[tid]=f0; gi_s[300+tid]=f1; gi_s[600+tid]=f2; gi_s[900+tid]=f3;
                }
            } else if (tid<600){
                if (fl){
                    int jq=tid-300;
                    u64 a01=dup2(g_bfb[lvl*G3+jq]), a23=a01;
                    const ulonglong2* dp=(const ulonglong2*)dec4;
                    const float* Fp=g_Fb + (lvl*50)*G3 + jq;
                    #pragma unroll 10
                    for (int k=0;k<50;k++){
                        u64 w=dup2(Fp[k*G3]);
                        ulonglong2 x=dp[k];
                        a01=ffma2(x.x,w,a01); a23=ffma2(x.y,w,a23);
                    }
                    float f0,f1,f2,f3;
                    asm("mov.b64 {%0,%1},%2;":"=f"(f0),"=f"(f1):"l"(a01));
                    asm("mov.b64 {%0,%1},%2;":"=f"(f2),"=f"(f3):"l"(a23));
                    gi_s[jq]=f0; gi_s[300+jq]=f1; gi_s[600+jq]=f2; gi_s[900+jq]=f3;
                }
            } else if (tid<856){
                int idx=tid-600;
                int r=idx>>6, dcol=idx&63;
                const float* mW=meanW+lvl*3200;
                float acc=meanB[lvl*64+dcol];
                #pragma unroll 10
                for (int k=0;k<50;k++) acc=fmaf(dec4[k*4+r], mW[k*64+dcol], acc);
                g_states[(tf*Bb+b0+r)*65+dcol]=acc;
            } else {
                if (tid<860) g_states[(tf*Bb+b0+(tid-856))*65+64]=1.f;
                if (fl){
                    int e=tid-856;
                    float v[6];
                    #pragma unroll
                    for (int q=0;q<6;q++){ int i2=e+q*72; v[q]=(i2<400)? g_dict[((tf+1)*128+blk)*400+i2] : 0.f; }
                    #pragma unroll
                    for (int q=0;q<6;q++){ int i2=e+q*72; if (i2<400) hb4f[i2]=v[q]; }
                }
            }
            __syncthreads();

            if (fl){
                int right=tf, left=curr_p+step/2;
                // right cell
                mv_reg(uB,hb4f,ghp,tid,j,kh,k0c,kcC);
                __syncthreads();
                gates4(ghp,gi_s,G3,sbb1,hb4f,g_dict+(right*128+blk)*400,tid);
                __syncthreads();
                // zeros-input chain
                for (int ii=right-1; ii>=left; ii--){
                    mv_reg(uB,hb4f,ghp,tid,j,kh,k0c,kcC);
                    __syncthreads();
                    gates4(ghp,sb0,0,sbb1,hb4f,g_dict+(ii*128+blk)*400,tid);
                    __syncthreads();
                }
            } else {
                skip=true;   // gi for tf is already in gi_s
            }
            obs_s[tf]=1;
        }
    }
}

__global__ void k_out(float* __restrict__ out){
    int idx=blockIdx.x*blockDim.x+threadIdx.x;
    if (idx>=Bb*Dd*Tt) return;
    int t=idx%Tt; int d=(idx/Tt)%Dd; int b=idx/(Tt*Dd);
    out[idx]=g_states[(t*Bb+b)*65 + d + 1];
}

extern "C" void kernel_launch(void* const* d_in, const int* in_sizes, int n_in,
                              void* d_out, int out_size){
    const float* a    =(const float*)d_in[0];
    const float* gruW =(const float*)d_in[1];
    const float* gruU =(const float*)d_in[2];
    const float* gruB =(const float*)d_in[3];
    const float* bgruW=(const float*)d_in[4];
    const float* bgruU=(const float*)d_in[5];
    const float* bgruB=(const float*)d_in[6];
    const float* decW =(const float*)d_in[7];
    const float* decB =(const float*)d_in[8];
    const float* meanW=(const float*)d_in[9];
    const float* meanB=(const float*)d_in[10];
    float* out=(float*)d_out;

    cudaFuncSetAttribute(k_fwd, cudaFuncAttributeMaxDynamicSharedMemorySize, 37500*4);

    k_sched<<<1,256>>>(a);
    k_states<<<(Tt*Bb*65+255)/256,256>>>(a);
    k_fuse<<<dim3(4,51),G3>>>(gruW,gruB,bgruW,bgruB,meanW,meanB);
    dim3 g2(Tt*32,2);
    k_gi<<<g2,320>>>(gruW,gruB,bgruW,bgruB);
    k_back<<<Bb/RPB,NTHR>>>(bgruU,bgruB);
    k_fwd<<<Bb/RPB,NTHR,37500*4>>>(gruU,gruB,bgruU,bgruB,decW,decB,meanW,meanB);
    k_out<<<(Bb*Dd*Tt+255)/256,256>>>(out);
}

// round 11
// speedup vs baseline: 1.5611x; 1.1388x over previous
#include <cuda_runtime.h>
#include <math.h>

#define Bb   512
#define Dd   64
#define Tt   256
#define RNN  100
#define G3   300
#define RPB  4
#define NTHR 928

typedef unsigned long long u64;

__device__ float g_states[Tt*Bb*65];
__device__ float g_gib[Tt*Bb*G3];
__device__ float g_gif[Tt*Bb*G3];
__device__ float g_dict[257*128*400];   // interleaved [key][blk][k*4+r]
__device__ int   g_obs[Tt];
__device__ float g_Ff[4*50*G3];         // fused fwd-gi  [lvl][k][j]
__device__ float g_Fb[4*50*G3];         // fused bwd-gi  [lvl][k][j]
__device__ float g_bff[4*G3];
__device__ float g_bfb[4*G3];

__device__ __forceinline__ float tanh_ap(float x){ float r; asm("tanh.approx.f32 %0, %1;":"=f"(r):"f"(x)); return r; }
__device__ __forceinline__ float sigm2(float x){ return 0.5f + 0.5f*tanh_ap(0.5f*x); }
__device__ __forceinline__ u64 ffma2(u64 a,u64 b,u64 c){ u64 d; asm("fma.rn.f32x2 %0, %1, %2, %3;":"=l"(d):"l"(a),"l"(b),"l"(c)); return d; }
__device__ __forceinline__ u64 dup2(float x){ u64 d; asm("mov.b64 %0, {%1, %1};":"=l"(d):"f"(x)); return d; }

__device__ __forceinline__ void st_ghp(float* ghp,int kh,int j,u64 a01,u64 a23){
    float f0,f1,f2,f3;
    asm("mov.b64 {%0,%1},%2;":"=f"(f0),"=f"(f1):"l"(a01));
    asm("mov.b64 {%0,%1},%2;":"=f"(f2),"=f"(f3):"l"(a23));
    float* p=ghp+kh*1200+j;
    p[0]=f0; p[300]=f1; p[600]=f2; p[900]=f3;
}

__device__ __forceinline__ void mv_reg(const float (&u)[34], const float* h4f, float* ghp,
                                       int tid,int j,int kh,int k0,int kc){
    if (tid<900){
        u64 a01=0ull, a23=0ull;
        const ulonglong2* h2=(const ulonglong2*)h4f;
        #pragma unroll
        for (int i=0;i<34;i++) if (i<kc){
            u64 w=dup2(u[i]);
            ulonglong2 x=h2[k0+i];
            a01=ffma2(x.x,w,a01); a23=ffma2(x.y,w,a23);
        }
        st_ghp(ghp,kh,j,a01,a23);
    }
}
__device__ __forceinline__ void mv_smem(const float* __restrict__ U, const float* h4f, float* ghp,
                                        int tid,int j,int kh,int k0,int kc){
    if (tid<900){
        u64 a01=0ull, a23=0ull;
        const ulonglong2* h2=(const ulonglong2*)h4f;
        #pragma unroll
        for (int i=0;i<34;i++) if (i<kc){
            u64 w=dup2(U[(k0+i)*G3+j]);
            ulonglong2 x=h2[k0+i];
            a01=ffma2(x.x,w,a01); a23=ffma2(x.y,w,a23);
        }
        st_ghp(ghp,kh,j,a01,a23);
    }
}

__device__ __forceinline__ void gates4(const float* ghp, const float* gi, int giStride,
                                       const float* b1s, float* h4f, float* dictDst, int tid){
    if (tid<400){
        int jj=tid>>2, r=tid&3;
        int o=r*300+jj;
        float ghz=ghp[o]    +ghp[1200+o]    +ghp[2400+o]    +b1s[jj];
        float ghr=ghp[o+100]+ghp[1200+o+100]+ghp[2400+o+100]+b1s[jj+100];
        float ghn=ghp[o+200]+ghp[1200+o+200]+ghp[2400+o+200]+b1s[jj+200];
        const float* g=gi+r*giStride;
        float z =sigm2(g[jj]     + ghz);
        float rr=sigm2(g[jj+100] + ghr);
        float n =tanh_ap(g[jj+200] + rr*ghn);
        float hn=z*h4f[tid]+(1.f-z)*n;
        h4f[tid]=hn;
        if (dictDst) dictDst[tid]=hn;
    }
}

__global__ void k_sched(const float* __restrict__ a){
    int t=threadIdx.x;
    if (t<Tt) g_obs[t] = (a[t*3+2] > 0.5f) ? 1 : 0;
}

__global__ void k_states(const float* __restrict__ a){
    int idx=blockIdx.x*blockDim.x+threadIdx.x;
    if (idx>=Tt*Bb*65) return;
    int c=idx%65; int b=(idx/65)%Bb; int t=idx/(65*Bb);
    float v=(c<64)? a[((b*Dd+c)*Tt+t)*3] : a[((b*Dd)*Tt+t)*3+2];
    g_states[(t*Bb+b)*65+c]=v;
}

// fused fill matrices (see R7 derivation)
__global__ void k_fuse(const float* __restrict__ gruW, const float* __restrict__ gruB,
                       const float* __restrict__ bgruW, const float* __restrict__ bgruB,
                       const float* __restrict__ meanW, const float* __restrict__ meanB){
    int lvl=blockIdx.x, j=threadIdx.x;
    if (j>=G3) return;
    int kk=blockIdx.y;
    const float* mW=meanW+lvl*3200;
    const float* mb=meanB+lvl*64;
    if (kk<50){
        float sf=0.f, sb=0.f;
        for (int m=0;m<64;m++){
            float w=mW[kk*64+m];
            if (m>=1) sf=fmaf(w, gruW[(m-1)*G3+j], sf);
            sb=fmaf(w, bgruW[m*G3+j], sb);
        }
        g_Ff[(lvl*50+kk)*G3+j]=sf;
        g_Fb[(lvl*50+kk)*G3+j]=sb;
    } else {
        float bf=gruB[j]+gruW[63*G3+j];
        float bb=bgruB[j]+bgruW[64*G3+j];
        for (int m=0;m<64;m++){
            if (m>=1) bf=fmaf(mb[m], gruW[(m-1)*G3+j], bf);
            bb=fmaf(mb[m], bgruW[m*G3+j], bb);
        }
        g_bff[lvl*G3+j]=bf;
        g_bfb[lvl*G3+j]=bb;
    }
}

// gi precompute, float4-vectorized x reads (stride 68 = 17 float4 per row).
// mode0: backward, t>=1, K=65 (16 chunks + scalar k=64), x stored at col c.
// mode1: forward, t==0 or observed, K=64 (16 chunks), mask col dropped at store.
__global__ void __launch_bounds__(320) k_gi(const float* __restrict__ gruW, const float* __restrict__ gruB,
                                            const float* __restrict__ bgruW, const float* __restrict__ bgruB){
    __shared__ __align__(16) float xs[16*68];
    int t=blockIdx.x>>5;
    int b0=(blockIdx.x&31)*16;
    int mode=blockIdx.y;
    if (mode==0 && t==0) return;
    if (mode==1 && t>0 && !g_obs[t]) return;
    int tid=threadIdx.x;
    for (int i=tid;i<16*65;i+=320){
        int r=i/65,c=i-r*65;
        float v=g_states[(t*Bb+b0+r)*65+c];
        if (mode==0)          xs[r*68+c]=v;
        else if (c>=1)        xs[r*68+c-1]=v;
    }
    __syncthreads();
    if (tid>=G3) return;
    const float* W = mode? gruW : bgruW;
    float bias     = mode? gruB[tid] : bgruB[tid];
    float acc[16];
    #pragma unroll
    for (int r=0;r<16;r++) acc[r]=bias;
    const float4* xs4=(const float4*)xs;
    #pragma unroll 4
    for (int c4=0;c4<16;c4++){
        float w0=W[(4*c4+0)*G3+tid];
        float w1=W[(4*c4+1)*G3+tid];
        float w2=W[(4*c4+2)*G3+tid];
        float w3=W[(4*c4+3)*G3+tid];
        #pragma unroll
        for (int r=0;r<16;r++){
            float4 v=xs4[r*17+c4];
            acc[r]=fmaf(v.x,w0,acc[r]);
            acc[r]=fmaf(v.y,w1,acc[r]);
            acc[r]=fmaf(v.z,w2,acc[r]);
            acc[r]=fmaf(v.w,w3,acc[r]);
        }
    }
    if (mode==0){
        float w=W[64*G3+tid];
        #pragma unroll
        for (int r=0;r<16;r++) acc[r]=fmaf(xs[r*68+64],w,acc[r]);
    }
    float* out = mode? g_gif : g_gib;
    #pragma unroll
    for (int r=0;r<16;r++) out[(t*Bb+b0+r)*G3+tid]=acc[r];
}

__global__ void __launch_bounds__(NTHR,1) k_back(const float* __restrict__ bgruU, const float* __restrict__ bgruB){
    __shared__ float ghp[3600];
    __shared__ float gi_s[1200];
    __shared__ __align__(16) float h4f[400];
    __shared__ float sbb1[300];
    int tid=threadIdx.x, blk=blockIdx.x, b0=blk*RPB;
    int kh=tid/300, j=tid-kh*300;
    int k0c=(kh==0)?0:((kh==1)?34:67);
    int kcC=(kh==0)?34:33;
    float uB[34];
    if (tid<900){
        #pragma unroll
        for (int i=0;i<34;i++) if (i<kcC) uB[i]=bgruU[(k0c+i)*G3+j];
    }
    if (tid<G3) sbb1[tid]=bgruB[G3+tid];
    if (tid<400){ h4f[tid]=0.f; g_dict[(256*128+blk)*400+tid]=0.f; }
    __syncthreads();
    for (int t=Tt-1;t>=1;t--){
        const float* src=g_gib+(t*Bb+b0)*G3;
        float f0=src[tid];
        float f1=(tid<272)? src[tid+NTHR] : 0.f;
        mv_reg(uB,h4f,ghp,tid,j,kh,k0c,kcC);
        gi_s[tid]=f0;
        if (tid<272) gi_s[tid+NTHR]=f1;
        __syncthreads();
        gates4(ghp,gi_s,G3,sbb1,h4f,(t>=2)? g_dict+(t*128+blk)*400 : (float*)0, tid);
        __syncthreads();
    }
}

// dyn smem (words): sUg 0..30000 | ghp 30000..33600 | gi_s 33600..34800 | h4f 34800..35200
// | hb4f 35200..35600 | dec4 35600..35800 | decp 35800..36600 | sb0 36600..36900
// | sbb1 36900..37200 | sgb1 37200..37500   total 37500 words = 150000 B
__global__ void __launch_bounds__(NTHR,1) k_fwd(
        const float* __restrict__ gruU, const float* __restrict__ gruB,
        const float* __restrict__ bgruU, const float* __restrict__ bgruB,
        const float* __restrict__ decW, const float* __restrict__ decB,
        const float* __restrict__ meanW, const float* __restrict__ meanB){
    extern __shared__ float sm[];
    float* sUg =sm;
    float* ghp =sm+30000;
    float* gi_s=sm+33600;
    float* h4f =sm+34800;
    float* hb4f=sm+35200;
    float* dec4=sm+35600;
    float* decp=sm+35800;
    float* sb0 =sm+36600;
    float* sbb1=sm+36900;
    float* sgb1=sm+37200;
    __shared__ int obs_s[Tt];

    int tid=threadIdx.x, blk=blockIdx.x, b0=blk*RPB;
    int kh=tid/300, j=tid-kh*300;
    int k0c=(kh==0)?0:((kh==1)?34:67);
    int kcC=(kh==0)?34:33;
    float uB[34];
    if (tid<900){
        #pragma unroll
        for (int i=0;i<34;i++) if (i<kcC) uB[i]=bgruU[(k0c+i)*G3+j];
    }
    for (int i=tid;i<RNN*G3;i+=NTHR) sUg[i]=gruU[i];
    if (tid<G3){ sb0[tid]=bgruB[tid]; sbb1[tid]=bgruB[G3+tid]; sgb1[tid]=gruB[G3+tid]; }
    if (tid<400) h4f[tid]=0.f;
    if (tid<Tt) obs_s[tid]=g_obs[tid];
    __syncthreads();

    bool skip=false;
    // initial forward cell: t=0
    {
        const float* src=g_gif+(0*Bb+b0)*G3;
        float f0=src[tid];
        float f1=(tid<272)? src[tid+NTHR] : 0.f;
        mv_smem(sUg,h4f,ghp,tid,j,kh,k0c,kcC);
        gi_s[tid]=f0;
        if (tid<272) gi_s[tid+NTHR]=f1;
        __syncthreads();
        gates4(ghp,gi_s,G3,sgb1,h4f,(float*)0,tid);
        __syncthreads();
    }

    int curr_p=0;
    while (curr_p < Tt-1){
        if (obs_s[curr_p+1]){
            curr_p++;
            float f0=0.f,f1=0.f;
            if (!skip){
                const float* src=g_gif+(curr_p*Bb+b0)*G3;
                f0=src[tid];
                if (tid<272) f1=src[tid+NTHR];
            }
            mv_smem(sUg,h4f,ghp,tid,j,kh,k0c,kcC);
            if (!skip){
                gi_s[tid]=f0;
                if (tid<272) gi_s[tid+NTHR]=f1;
            }
            skip=false;
            __syncthreads();
            gates4(ghp,gi_s,G3,sgb1,h4f,(float*)0,tid);
            __syncthreads();
        } else {
            int next_p=curr_p+1;
            while (next_p<Tt && !obs_s[next_p]) next_p++;
            int step=1;
            while (curr_p+2*step<=next_p && step<=8) step<<=1;
            if (step>1) step>>=1;
            int lvl=(step==8)?3:((step==4)?2:((step==2)?1:0));
            int tf=curr_p+step;
            int fl=(step>1);

            // P1: hb = dict[curr+2*step]
            if (tid<400) hb4f[tid]=g_dict[((curr_p+2*step)*128+blk)*400+tid];
            __syncthreads();

            // P2: decoder partials over cat[h,hb] (full unroll -> MLP 50)
            if (tid<800){
                int seg=tid/200, o=tid-seg*200;
                int r=o/50, jo=o-r*50;
                const float* dW=decW+lvl*10000+(seg*50)*50+jo;
                const float* hsrc=(seg<2)? (h4f+(seg&1)*200) : (hb4f+(seg&1)*200);
                float acc=0.f;
                #pragma unroll
                for (int kk=0;kk<50;kk++)
                    acc=fmaf(hsrc[kk*4+r], dW[kk*50], acc);
                decp[seg*200+o]=acc;
            }
            __syncthreads();

            // P3: reduce + relu -> dec4 interleaved [k*4+r]
            if (tid<200){
                int r=tid/50, jo=tid-r*50;
                int o=r*50+jo;
                float v=decp[o]+decp[200+o]+decp[400+o]+decp[600+o]+decB[lvl*50+jo];
                dec4[jo*4+r]=fmaxf(v,0.f);
            }
            __syncthreads();

            // P4: merged — fwd-gi || bwd-gi(if fl) || mean || hb(right+1) prefetch
            if (tid<300){
                u64 a01=dup2(g_bff[lvl*G3+tid]), a23=a01;
                const ulonglong2* dp=(const ulonglong2*)dec4;
                const float* Fp=g_Ff + (lvl*50)*G3 + tid;
                #pragma unroll
                for (int k=0;k<50;k++){
                    u64 w=dup2(Fp[k*G3]);
                    ulonglong2 x=dp[k];
                    a01=ffma2(x.x,w,a01); a23=ffma2(x.y,w,a23);
                }
                float f0,f1,f2,f3;
                asm("mov.b64 {%0,%1},%2;":"=f"(f0),"=f"(f1):"l"(a01));
                asm("mov.b64 {%0,%1},%2;":"=f"(f2),"=f"(f3):"l"(a23));
                float* dst=g_gif+(tf*Bb+b0)*G3+tid;
                dst[0]=f0; dst[300]=f1; dst[600]=f2; dst[900]=f3;
                if (!fl){
                    gi_s[tid]=f0; gi_s[300+tid]=f1; gi_s[600+tid]=f2; gi_s[900+tid]=f3;
                }
            } else if (tid<600){
                if (fl){
                    int jq=tid-300;
                    u64 a01=dup2(g_bfb[lvl*G3+jq]), a23=a01;
                    const ulonglong2* dp=(const ulonglong2*)dec4;
                    const float* Fp=g_Fb + (lvl*50)*G3 + jq;
                    #pragma unroll
                    for (int k=0;k<50;k++){
                        u64 w=dup2(Fp[k*G3]);
                        ulonglong2 x=dp[k];
                        a01=ffma2(x.x,w,a01); a23=ffma2(x.y,w,a23);
                    }
                    float f0,f1,f2,f3;
                    asm("mov.b64 {%0,%1},%2;":"=f"(f0),"=f"(f1):"l"(a01));
                    asm("mov.b64 {%0,%1},%2;":"=f"(f2),"=f"(f3):"l"(a23));
                    gi_s[jq]=f0; gi_s[300+jq]=f1; gi_s[600+jq]=f2; gi_s[900+jq]=f3;
                }
            } else if (tid<856){
                int idx=tid-600;
                int r=idx>>6, dcol=idx&63;
                const float* mW=meanW+lvl*3200;
                float acc=meanB[lvl*64+dcol];
                #pragma unroll
                for (int k=0;k<50;k++) acc=fmaf(dec4[k*4+r], mW[k*64+dcol], acc);
                g_states[(tf*Bb+b0+r)*65+dcol]=acc;
            } else {
                if (tid<860) g_states[(tf*Bb+b0+(tid-856))*65+64]=1.f;
                if (fl){
                    int e=tid-856;
                    float v[6];
                    #pragma unroll
                    for (int q=0;q<6;q++){ int i2=e+q*72; v[q]=(i2<400)? g_dict[((tf+1)*128+blk)*400+i2] : 0.f; }
                    #pragma unroll
                    for (int q=0;q<6;q++){ int i2=e+q*72; if (i2<400) hb4f[i2]=v[q]; }
                }
            }
            __syncthreads();

            if (fl){
                int right=tf, left=curr_p+step/2;
                mv_reg(uB,hb4f,ghp,tid,j,kh,k0c,kcC);
                __syncthreads();
                gates4(ghp,gi_s,G3,sbb1,hb4f,g_dict+(right*128+blk)*400,tid);
                __syncthreads();
                for (int ii=right-1; ii>=left; ii--){
                    mv_reg(uB,hb4f,ghp,tid,j,kh,k0c,kcC);
                    __syncthreads();
                    gates4(ghp,sb0,0,sbb1,hb4f,g_dict+(ii*128+blk)*400,tid);
                    __syncthreads();
                }
            } else {
                skip=true;
            }
            obs_s[tf]=1;
        }
    }
}

__global__ void k_out(float* __restrict__ out){
    int idx=blockIdx.x*blockDim.x+threadIdx.x;
    if (idx>=Bb*Dd*Tt) return;
    int t=idx%Tt; int d=(idx/Tt)%Dd; int b=idx/(Tt*Dd);
    out[idx]=g_states[(t*Bb+b)*65 + d + 1];
}

extern "C" void kernel_launch(void* const* d_in, const int* in_sizes, int n_in,
                              void* d_out, int out_size){
    const float* a    =(const float*)d_in[0];
    const float* gruW =(const float*)d_in[1];
    const float* gruU =(const float*)d_in[2];
    const float* gruB =(const float*)d_in[3];
    const float* bgruW=(const float*)d_in[4];
    const float* bgruU=(const float*)d_in[5];
    const float* bgruB=(const float*)d_in[6];
    const float* decW =(const float*)d_in[7];
    const float* decB =(const float*)d_in[8];
    const float* meanW=(const float*)d_in[9];
    const float* meanB=(const float*)d_in[10];
    float* out=(float*)d_out;

    cudaFuncSetAttribute(k_fwd, cudaFuncAttributeMaxDynamicSharedMemorySize, 37500*4);

    k_sched<<<1,256>>>(a);
    k_states<<<(Tt*Bb*65+255)/256,256>>>(a);
    k_fuse<<<dim3(4,51),G3>>>(gruW,gruB,bgruW,bgruB,meanW,meanB);
    dim3 g2(Tt*32,2);
    k_gi<<<g2,320>>>(gruW,gruB,bgruW,bgruB);
    k_back<<<Bb/RPB,NTHR>>>(bgruU,bgruB);
    k_fwd<<<Bb/RPB,NTHR,37500*4>>>(gruU,gruB,bgruU,bgruB,decW,decB,meanW,meanB);
    k_out<<<(Bb*Dd*Tt+255)/256,256>>>(out);
}